// round 15
// baseline (speedup 1.0000x reference)
#include <cuda_runtime.h>
#include <cuda_fp16.h>

#define NN 100000
#define NE 3200000
#define NG 64
#define F  64

// ---- scratch (static device globals; no dynamic allocation) ----
__device__ int    g_cnt[NN];          // in-degree (real edges) per dst
__device__ int    g_cur[NN];          // fill cursor per dst
__device__ int    g_rowptr[NN];       // CSR row start (exclusive scan of g_cnt)
__device__ int    g_bsum[128];        // block sums for scan
__device__ float  g_dinv[NN];         // deg^-1/2 (with self loop)
__device__ int2   g_edge[NE];         // CSR: {src, w_bits} packed, grouped by dst
__device__ __half2 g_h[(size_t)NN * 32];    // h = relu(conv(x)@W1+b1)  fp16 [N,64]
__device__ float  g_pool[NG * F];
__device__ int    g_gcnt[NG];

// ---------------- init ----------------
__global__ void k_zero() {
    int i = blockIdx.x * blockDim.x + threadIdx.x;
    if (i < NN) { g_cnt[i] = 0; g_cur[i] = 0; }
    if (i < NG * F) g_pool[i] = 0.f;
    if (i < NG) g_gcnt[i] = 0;
}

// ---------------- degree histogram over dst (int4-vectorized: NE % 4 == 0) ----------------
__global__ void k_hist(const int* __restrict__ ei) {
    int stride = gridDim.x * blockDim.x;
    const int4* d4 = (const int4*)(ei + NE);
    for (int e = blockIdx.x * blockDim.x + threadIdx.x; e < NE / 4; e += stride) {
        int4 d = __ldg(&d4[e]);
        atomicAdd(&g_cnt[d.x], 1);
        atomicAdd(&g_cnt[d.y], 1);
        atomicAdd(&g_cnt[d.z], 1);
        atomicAdd(&g_cnt[d.w], 1);
    }
}

// ---------------- per-graph node counts, warp-aggregated ----------------
__global__ void k_gcnt(const int* __restrict__ batch) {
    int i = blockIdx.x * blockDim.x + threadIdx.x;
    if (i >= NN) return;
    int b = batch[i];
    unsigned m = __match_any_sync(__activemask(), b);
    int leader = __ffs(m) - 1;
    if ((threadIdx.x & 31) == leader)
        atomicAdd(&g_gcnt[b], __popc(m));
}

// ---------------- exclusive scan of g_cnt -> g_rowptr (warp-shuffle) ----------------
__global__ void k_scanA() {
    __shared__ int wsum[32];
    int i = blockIdx.x * 1024 + threadIdx.x;
    int lane = threadIdx.x & 31, warp = threadIdx.x >> 5;
    int v = (i < NN) ? g_cnt[i] : 0;
    int s = v;
#pragma unroll
    for (int off = 1; off < 32; off <<= 1) {
        int t = __shfl_up_sync(0xffffffffu, s, off);
        if (lane >= off) s += t;
    }
    if (lane == 31) wsum[warp] = s;
    __syncthreads();
    if (warp == 0) {
        int w = wsum[lane];
        int ws = w;
#pragma unroll
        for (int off = 1; off < 32; off <<= 1) {
            int t = __shfl_up_sync(0xffffffffu, ws, off);
            if (lane >= off) ws += t;
        }
        wsum[lane] = ws - w;   // exclusive warp offsets
        if (lane == 31) g_bsum[blockIdx.x] = ws;  // block total
    }
    __syncthreads();
    if (i < NN) g_rowptr[i] = s - v + wsum[warp];
}

__global__ void k_scanB(int nb) {
    if (threadIdx.x == 0) {
        int run = 0;
        for (int i = 0; i < nb; i++) { int t = g_bsum[i]; g_bsum[i] = run; run += t; }
    }
}

// rowptr block offsets + dinv in one pass
__global__ void k_scanC() {
    int i = blockIdx.x * blockDim.x + threadIdx.x;
    if (i < NN) {
        g_rowptr[i] += g_bsum[i >> 10];
        g_dinv[i] = rsqrtf((float)(g_cnt[i] + 1));  // +1 self loop
    }
}

// ---------------- CSR fill: packed {src, weight} ----------------
__global__ void k_fill(const int* __restrict__ ei) {
    int stride = gridDim.x * blockDim.x;
    for (int e = blockIdx.x * blockDim.x + threadIdx.x; e < NE; e += stride) {
        int s = ei[e];
        int d = ei[NE + e];
        float w = g_dinv[s] * g_dinv[d];
        int pos = g_rowptr[d] + atomicAdd(&g_cur[d], 1);
        g_edge[pos] = make_int2(s, __float_as_int(w));
    }
}

// ---------------- fused: h = relu(conv(x) @ W1 + b1) -> fp16, warp per node ----------------
__global__ void k_conv3h(const float* __restrict__ x, const float* __restrict__ W1,
                         const float* __restrict__ b1) {
    int n = blockIdx.x * 8 + (threadIdx.x >> 5);
    int lane = threadIdx.x & 31;
    if (n >= NN) return;
    // lane owns output features 2*lane, 2*lane+1
    int f0 = lane * 2;
    float w00 = __ldg(&W1[f0]),       w01 = __ldg(&W1[f0 + 1]);
    float w10 = __ldg(&W1[64 + f0]),  w11 = __ldg(&W1[64 + f0 + 1]);
    float w20 = __ldg(&W1[128 + f0]), w21 = __ldg(&W1[128 + f0 + 1]);
    float bb0 = __ldg(&b1[f0]),       bb1 = __ldg(&b1[f0 + 1]);

    int r0 = g_rowptr[n];
    int r1 = r0 + g_cnt[n];
    float a0 = 0.f, a1 = 0.f, a2 = 0.f;
    for (int i = r0 + lane; i < r1; i += 32) {
        int2 e = __ldg(&g_edge[i]);
        float w = __int_as_float(e.y);
        int s = e.x;
        a0 += w * __ldg(&x[s * 3]);
        a1 += w * __ldg(&x[s * 3 + 1]);
        a2 += w * __ldg(&x[s * 3 + 2]);
    }
#pragma unroll
    for (int off = 16; off > 0; off >>= 1) {
        a0 += __shfl_down_sync(0xffffffffu, a0, off);
        a1 += __shfl_down_sync(0xffffffffu, a1, off);
        a2 += __shfl_down_sync(0xffffffffu, a2, off);
    }
    if (lane == 0) {
        float dn = g_dinv[n], sw = dn * dn;
        a0 += sw * __ldg(&x[n * 3]);
        a1 += sw * __ldg(&x[n * 3 + 1]);
        a2 += sw * __ldg(&x[n * 3 + 2]);
    }
    a0 = __shfl_sync(0xffffffffu, a0, 0);
    a1 = __shfl_sync(0xffffffffu, a1, 0);
    a2 = __shfl_sync(0xffffffffu, a2, 0);
    float v0 = fmaxf(bb0 + a0 * w00 + a1 * w10 + a2 * w20, 0.f);
    float v1 = fmaxf(bb1 + a0 * w01 + a1 * w11 + a2 * w21, 0.f);
    g_h[(size_t)n * 32 + lane] = __floats2half2_rn(v0, v1);
}

// ---------------- fused: conv(h) -> smem -> relu(@W2+b2) -> pool ----------------
__global__ void k_convg2p(const float* __restrict__ W2, const float* __restrict__ b2,
                          const int* __restrict__ batch) {
    __shared__ float W2s[64 * 64];          // [k*64 + f]
    __shared__ float hs[32 * 68];           // 32 node rows, padded
    __shared__ float red[4 * 64];           // grp partial sums per feature
    int tid = threadIdx.x;
    int warp = tid >> 5, lane = tid & 31;
    int nbase = blockIdx.x * 32;

    for (int i = tid; i < 4096; i += 256) W2s[i] = W2[i];

    // conv: warp handles local nodes warp, warp+8, warp+16, warp+24
#pragma unroll
    for (int r = 0; r < 4; r++) {
        int node = warp + r * 8;
        int n = nbase + node;
        int r0 = g_rowptr[n];
        int r1 = r0 + g_cnt[n];
        float ax = 0.f, ay = 0.f;
#pragma unroll 4
        for (int i = r0; i < r1; i++) {
            int2 e = __ldg(&g_edge[i]);          // broadcast 8B
            float w = __int_as_float(e.y);
            float2 v = __half22float2(__ldg(&g_h[(size_t)e.x * 32 + lane]));
            ax += w * v.x;
            ay += w * v.y;
        }
        float dn = g_dinv[n], sw = dn * dn;
        float2 v = __half22float2(__ldg(&g_h[(size_t)n * 32 + lane]));
        ax += sw * v.x;
        ay += sw * v.y;
        *(float2*)&hs[node * 68 + lane * 2] = make_float2(ax, ay);
    }
    __syncthreads();

    // GEMM: grp owns 8 nodes, f = feature column
    int f = tid & 63, grp = tid >> 6;
    float bf = __ldg(&b2[f]);
    float acc[8];
#pragma unroll
    for (int i = 0; i < 8; i++) acc[i] = bf;
#pragma unroll 4
    for (int k4 = 0; k4 < 64; k4 += 4) {
        float4 hv[8];
#pragma unroll
        for (int i = 0; i < 8; i++)
            hv[i] = *(const float4*)&hs[(grp * 8 + i) * 68 + k4];
#pragma unroll
        for (int j = 0; j < 4; j++) {
            float wk = W2s[(k4 + j) * 64 + f];
#pragma unroll
            for (int i = 0; i < 8; i++) {
                float h = (j == 0) ? hv[i].x : (j == 1) ? hv[i].y : (j == 2) ? hv[i].z : hv[i].w;
                acc[i] += h * wk;
            }
        }
    }
    int b_lo = __ldg(&batch[nbase]);
    int b_hi = __ldg(&batch[nbase + 31]);
    if (b_lo == b_hi) {
        // whole block is one graph: block-reduce then 64 atomics
        float p = 0.f;
#pragma unroll
        for (int i = 0; i < 8; i++) p += fmaxf(acc[i], 0.f);
        red[grp * 64 + f] = p;
        __syncthreads();
        if (grp == 0) {
            float s = red[f] + red[64 + f] + red[128 + f] + red[192 + f];
            atomicAdd(&g_pool[b_lo * 64 + f], s);
        }
    } else {
        // boundary block (rare): per-node atomics
#pragma unroll
        for (int i = 0; i < 8; i++) {
            int node = nbase + grp * 8 + i;
            atomicAdd(&g_pool[__ldg(&batch[node]) * 64 + f], fmaxf(acc[i], 0.f));
        }
    }
}

// ---------------- out[g] = (sum_f pool[g][f]*Wr[f]) / count + br ----------------
__global__ void k_final(const float* __restrict__ Wr, const float* __restrict__ br,
                        float* __restrict__ out) {
    int g = threadIdx.x;
    if (g >= NG) return;
    float s = 0.f;
#pragma unroll
    for (int f = 0; f < 64; f++) s += g_pool[g * 64 + f] * Wr[f];
    out[g] = s / fmaxf((float)g_gcnt[g], 1.f) + br[0];
}

extern "C" void kernel_launch(void* const* d_in, const int* in_sizes, int n_in,
                              void* d_out, int out_size) {
    const float* x     = (const float*)d_in[0];
    const int*   ei    = (const int*)d_in[1];     // int32
    const int*   batch = (const int*)d_in[2];     // int32
    const float* W1    = (const float*)d_in[3];
    const float* b1    = (const float*)d_in[4];
    const float* W2    = (const float*)d_in[5];
    const float* b2    = (const float*)d_in[6];
    const float* Wr    = (const float*)d_in[7];
    const float* br    = (const float*)d_in[8];
    float*       out   = (float*)d_out;

    (void)in_sizes; (void)n_in; (void)out_size;

    const int nb = (NN + 1023) / 1024;  // 98 scan blocks

    k_zero<<<(NN + 255) / 256, 256>>>();
    k_hist<<<2048, 256>>>(ei);
    k_gcnt<<<(NN + 255) / 256, 256>>>(batch);
    k_scanA<<<nb, 1024>>>();
    k_scanB<<<1, 32>>>(nb);
    k_scanC<<<(NN + 255) / 256, 256>>>();     // rowptr offsets + dinv
    k_fill<<<4096, 256>>>(ei);

    k_conv3h<<<(NN + 7) / 8, 256>>>(x, W1, b1);   // h = relu(conv(x)@W1+b1) fp16
    k_convg2p<<<NN / 32, 256>>>(W2, b2, batch);   // pool(relu(conv(h)@W2+b2))

    k_final<<<1, 64>>>(Wr, br, out);
}

// round 16
// speedup vs baseline: 1.2043x; 1.2043x over previous
#include <cuda_runtime.h>
#include <cuda_fp16.h>

#define NN 100000
#define NE 3200000
#define NG 64
#define F  64

// ---- scratch (static device globals; no dynamic allocation) ----
__device__ int    g_cnt[NN];          // in-degree (real edges) per dst
__device__ int    g_cur[NN];          // fill cursor per dst
__device__ int    g_rowptr[NN];       // CSR row start (exclusive scan of g_cnt)
__device__ int    g_bsum[128];        // block sums for scan
__device__ float  g_dinv[NN];         // deg^-1/2 (with self loop)
__device__ int2   g_edge[NE];         // CSR: {src, dinv[src]_bits}, grouped by dst
__device__ __half2 g_h[(size_t)NN * 32];    // h = relu(conv(x)@W1+b1)  fp16 [N,64]
__device__ float  g_C[(size_t)NN * F];      // conv(h)  [N,64] fp32
__device__ float  g_pool[NG * F];
__device__ int    g_gcnt[NG];

// ---------------- init ----------------
__global__ void k_zero() {
    int i = blockIdx.x * blockDim.x + threadIdx.x;
    if (i < NN) { g_cnt[i] = 0; g_cur[i] = 0; }
    if (i < NG * F) g_pool[i] = 0.f;
    if (i < NG) g_gcnt[i] = 0;
}

// ---------------- degree histogram over dst (int4-vectorized: NE % 4 == 0) ----------------
__global__ void k_hist(const int* __restrict__ ei) {
    int e = blockIdx.x * blockDim.x + threadIdx.x;
    if (e >= NE / 4) return;
    int4 d = __ldg(&((const int4*)(ei + NE))[e]);
    atomicAdd(&g_cnt[d.x], 1);
    atomicAdd(&g_cnt[d.y], 1);
    atomicAdd(&g_cnt[d.z], 1);
    atomicAdd(&g_cnt[d.w], 1);
}

// ---------------- per-graph node counts, warp-aggregated ----------------
__global__ void k_gcnt(const int* __restrict__ batch) {
    int i = blockIdx.x * blockDim.x + threadIdx.x;
    if (i >= NN) return;
    int b = batch[i];
    unsigned m = __match_any_sync(__activemask(), b);
    int leader = __ffs(m) - 1;
    if ((threadIdx.x & 31) == leader)
        atomicAdd(&g_gcnt[b], __popc(m));
}

// ---------------- exclusive scan of g_cnt -> g_rowptr (warp-shuffle) ----------------
__global__ void k_scanA() {
    __shared__ int wsum[32];
    int i = blockIdx.x * 1024 + threadIdx.x;
    int lane = threadIdx.x & 31, warp = threadIdx.x >> 5;
    int v = (i < NN) ? g_cnt[i] : 0;
    int s = v;
#pragma unroll
    for (int off = 1; off < 32; off <<= 1) {
        int t = __shfl_up_sync(0xffffffffu, s, off);
        if (lane >= off) s += t;
    }
    if (lane == 31) wsum[warp] = s;
    __syncthreads();
    if (warp == 0) {
        int w = wsum[lane];
        int ws = w;
#pragma unroll
        for (int off = 1; off < 32; off <<= 1) {
            int t = __shfl_up_sync(0xffffffffu, ws, off);
            if (lane >= off) ws += t;
        }
        wsum[lane] = ws - w;   // exclusive warp offsets
        if (lane == 31) g_bsum[blockIdx.x] = ws;  // block total
    }
    __syncthreads();
    if (i < NN) g_rowptr[i] = s - v + wsum[warp];
}

__global__ void k_scanB(int nb) {
    if (threadIdx.x == 0) {
        int run = 0;
        for (int i = 0; i < nb; i++) { int t = g_bsum[i]; g_bsum[i] = run; run += t; }
    }
}

// rowptr block offsets + dinv in one pass
__global__ void k_scanC() {
    int i = blockIdx.x * blockDim.x + threadIdx.x;
    if (i < NN) {
        g_rowptr[i] += g_bsum[i >> 10];
        g_dinv[i] = rsqrtf((float)(g_cnt[i] + 1));  // +1 self loop
    }
}

// ---------------- CSR fill: packed {src, dinv[src]} (dinv[dst] factored out) ----------------
__global__ void k_fill(const int* __restrict__ ei) {
    int e = blockIdx.x * blockDim.x + threadIdx.x;
    if (e >= NE / 4) return;
    int4 s4 = __ldg(&((const int4*)ei)[e]);
    int4 d4 = __ldg(&((const int4*)(ei + NE))[e]);
#pragma unroll
    for (int j = 0; j < 4; j++) {
        int s = (j == 0) ? s4.x : (j == 1) ? s4.y : (j == 2) ? s4.z : s4.w;
        int d = (j == 0) ? d4.x : (j == 1) ? d4.y : (j == 2) ? d4.z : d4.w;
        int pos = g_rowptr[d] + atomicAdd(&g_cur[d], 1);
        g_edge[pos] = make_int2(s, __float_as_int(g_dinv[s]));
    }
}

// ---------------- fused: h = relu(dinv[n]*conv(x) @ W1 + b1) -> fp16, warp per node ----------------
__global__ void k_conv3h(const float* __restrict__ x, const float* __restrict__ W1,
                         const float* __restrict__ b1) {
    int n = blockIdx.x * 8 + (threadIdx.x >> 5);
    int lane = threadIdx.x & 31;
    if (n >= NN) return;
    // lane owns output features 2*lane, 2*lane+1
    int f0 = lane * 2;
    float w00 = __ldg(&W1[f0]),       w01 = __ldg(&W1[f0 + 1]);
    float w10 = __ldg(&W1[64 + f0]),  w11 = __ldg(&W1[64 + f0 + 1]);
    float w20 = __ldg(&W1[128 + f0]), w21 = __ldg(&W1[128 + f0 + 1]);
    float bb0 = __ldg(&b1[f0]),       bb1 = __ldg(&b1[f0 + 1]);

    int r0 = g_rowptr[n];
    int r1 = r0 + g_cnt[n];
    float a0 = 0.f, a1 = 0.f, a2 = 0.f;
    for (int i = r0 + lane; i < r1; i += 32) {
        int2 e = __ldg(&g_edge[i]);
        float w = __int_as_float(e.y);      // dinv[src]
        int s = e.x;
        a0 += w * __ldg(&x[s * 3]);
        a1 += w * __ldg(&x[s * 3 + 1]);
        a2 += w * __ldg(&x[s * 3 + 2]);
    }
#pragma unroll
    for (int off = 16; off > 0; off >>= 1) {
        a0 += __shfl_down_sync(0xffffffffu, a0, off);
        a1 += __shfl_down_sync(0xffffffffu, a1, off);
        a2 += __shfl_down_sync(0xffffffffu, a2, off);
    }
    if (lane == 0) {
        float dn = g_dinv[n];
        a0 = dn * (a0 + dn * __ldg(&x[n * 3]));
        a1 = dn * (a1 + dn * __ldg(&x[n * 3 + 1]));
        a2 = dn * (a2 + dn * __ldg(&x[n * 3 + 2]));
    }
    a0 = __shfl_sync(0xffffffffu, a0, 0);
    a1 = __shfl_sync(0xffffffffu, a1, 0);
    a2 = __shfl_sync(0xffffffffu, a2, 0);
    float v0 = fmaxf(bb0 + a0 * w00 + a1 * w10 + a2 * w20, 0.f);
    float v1 = fmaxf(bb1 + a0 * w01 + a1 * w11 + a2 * w21, 0.f);
    g_h[(size_t)n * 32 + lane] = __floats2half2_rn(v0, v1);
}

// ---------------- conv64: g_C = dinv[n]*conv(h), warp per node (fp16 gather) ----------------
__global__ void k_conv64() {
    int n = blockIdx.x * 8 + (threadIdx.x >> 5);
    int lane = threadIdx.x & 31;
    if (n >= NN) return;
    int r0 = g_rowptr[n];
    int r1 = r0 + g_cnt[n];
    float ax = 0.f, ay = 0.f;
#pragma unroll 4
    for (int i = r0; i < r1; i++) {
        int2 e = __ldg(&g_edge[i]);          // broadcast 8B
        float w = __int_as_float(e.y);       // dinv[src]
        float2 v = __half22float2(__ldg(&g_h[(size_t)e.x * 32 + lane]));  // 128B row
        ax += w * v.x;
        ay += w * v.y;
    }
    float dn = g_dinv[n];
    float2 v = __half22float2(__ldg(&g_h[(size_t)n * 32 + lane]));
    ax = dn * (ax + dn * v.x);
    ay = dn * (ay + dn * v.y);
    ((float2*)g_C)[(size_t)n * 32 + lane] = make_float2(ax, ay);
}

// ---------------- relu(g_C @ W2 + b2), fused pooling ----------------
__global__ void k_g2p(const float* __restrict__ W2, const float* __restrict__ b2,
                      const int* __restrict__ batch) {
    __shared__ float W2s[64 * 64];          // [k*64 + f]
    __shared__ float hs[32 * 68];           // 32 node rows, padded
    __shared__ float red[4 * 64];           // grp partial sums per feature
    int tid = threadIdx.x;
    int nbase = blockIdx.x * 32;
    for (int i = tid; i < 4096; i += 256) W2s[i] = W2[i];
    for (int i = tid; i < 2048; i += 256) {
        int node = i >> 6, k = i & 63;
        hs[node * 68 + k] = g_C[(size_t)(nbase + node) * 64 + k];
    }
    __syncthreads();
    int f = tid & 63, grp = tid >> 6;       // grp owns 8 nodes
    float bf = __ldg(&b2[f]);
    float acc[8];
#pragma unroll
    for (int i = 0; i < 8; i++) acc[i] = bf;
#pragma unroll 4
    for (int k4 = 0; k4 < 64; k4 += 4) {
        float4 hv[8];
#pragma unroll
        for (int i = 0; i < 8; i++)
            hv[i] = *(const float4*)&hs[(grp * 8 + i) * 68 + k4];
#pragma unroll
        for (int j = 0; j < 4; j++) {
            float wk = W2s[(k4 + j) * 64 + f];
#pragma unroll
            for (int i = 0; i < 8; i++) {
                float h = (j == 0) ? hv[i].x : (j == 1) ? hv[i].y : (j == 2) ? hv[i].z : hv[i].w;
                acc[i] += h * wk;
            }
        }
    }
    int b_lo = __ldg(&batch[nbase]);
    int b_hi = __ldg(&batch[nbase + 31]);
    if (b_lo == b_hi) {
        // whole block is one graph: block-reduce then 64 atomics
        float p = 0.f;
#pragma unroll
        for (int i = 0; i < 8; i++) p += fmaxf(acc[i], 0.f);
        red[grp * 64 + f] = p;
        __syncthreads();
        if (grp == 0) {
            float s = red[f] + red[64 + f] + red[128 + f] + red[192 + f];
            atomicAdd(&g_pool[b_lo * 64 + f], s);
        }
    } else {
        // boundary block (rare): per-node atomics
#pragma unroll
        for (int i = 0; i < 8; i++) {
            int node = nbase + grp * 8 + i;
            atomicAdd(&g_pool[__ldg(&batch[node]) * 64 + f], fmaxf(acc[i], 0.f));
        }
    }
}

// ---------------- out[g] = (sum_f pool[g][f]*Wr[f]) / count + br ----------------
__global__ void k_final(const float* __restrict__ Wr, const float* __restrict__ br,
                        float* __restrict__ out) {
    int g = threadIdx.x;
    if (g >= NG) return;
    float s = 0.f;
#pragma unroll
    for (int f = 0; f < 64; f++) s += g_pool[g * 64 + f] * Wr[f];
    out[g] = s / fmaxf((float)g_gcnt[g], 1.f) + br[0];
}

extern "C" void kernel_launch(void* const* d_in, const int* in_sizes, int n_in,
                              void* d_out, int out_size) {
    const float* x     = (const float*)d_in[0];
    const int*   ei    = (const int*)d_in[1];     // int32
    const int*   batch = (const int*)d_in[2];     // int32
    const float* W1    = (const float*)d_in[3];
    const float* b1    = (const float*)d_in[4];
    const float* W2    = (const float*)d_in[5];
    const float* b2    = (const float*)d_in[6];
    const float* Wr    = (const float*)d_in[7];
    const float* br    = (const float*)d_in[8];
    float*       out   = (float*)d_out;

    (void)in_sizes; (void)n_in; (void)out_size;

    const int nb = (NN + 1023) / 1024;   // 98 scan blocks
    const int eb = (NE / 4 + 255) / 256; // 3125 edge-quad blocks

    k_zero<<<(NN + 255) / 256, 256>>>();
    k_hist<<<eb, 256>>>(ei);
    k_gcnt<<<(NN + 255) / 256, 256>>>(batch);
    k_scanA<<<nb, 1024>>>();
    k_scanB<<<1, 32>>>(nb);
    k_scanC<<<(NN + 255) / 256, 256>>>();     // rowptr offsets + dinv
    k_fill<<<eb, 256>>>(ei);

    k_conv3h<<<(NN + 7) / 8, 256>>>(x, W1, b1);   // h = relu(dinv*conv(x)@W1+b1) fp16
    k_conv64<<<(NN + 7) / 8, 256>>>();            // C = dinv*conv(h)
    k_g2p<<<NN / 32, 256>>>(W2, b2, batch);       // pool(relu(C@W2+b2))

    k_final<<<1, 64>>>(Wr, br, out);
}

// round 17
// speedup vs baseline: 1.2810x; 1.0637x over previous
#include <cuda_runtime.h>
#include <cuda_fp16.h>

#define NN 100000
#define NE 3200000
#define NG 64
#define F  64

// ---- scratch (static device globals; no dynamic allocation) ----
__device__ int    g_cnt[NN];          // in-degree (real edges) per dst
__device__ int    g_cur[NN];          // fill cursor per dst
__device__ int    g_rowptr[NN];       // CSR row start (exclusive scan of g_cnt)
__device__ int    g_bsum[128];        // block sums for scan
__device__ float  g_dinv[NN];         // deg^-1/2 (with self loop)
__device__ int    g_col[NE];          // CSR: src per edge, grouped by dst
__device__ float4 g_xs[NN];           // dinv[n]*x[n], padded to 16B
__device__ __half2 g_h[(size_t)NN * 32];    // hs = dinv*relu(conv(x)@W1+b1)  fp16 [N,64]
__device__ float  g_C[(size_t)NN * F];      // conv(h)  [N,64] fp32
__device__ float  g_pool[NG * F];
__device__ int    g_gcnt[NG];

// ---------------- init ----------------
__global__ void k_zero() {
    int i = blockIdx.x * blockDim.x + threadIdx.x;
    if (i < NN) { g_cnt[i] = 0; g_cur[i] = 0; }
    if (i < NG * F) g_pool[i] = 0.f;
    if (i < NG) g_gcnt[i] = 0;
}

// ---------------- degree histogram over dst (int4-vectorized: NE % 4 == 0) ----------------
__global__ void k_hist(const int* __restrict__ ei) {
    int e = blockIdx.x * blockDim.x + threadIdx.x;
    if (e >= NE / 4) return;
    int4 d = __ldg(&((const int4*)(ei + NE))[e]);
    atomicAdd(&g_cnt[d.x], 1);
    atomicAdd(&g_cnt[d.y], 1);
    atomicAdd(&g_cnt[d.z], 1);
    atomicAdd(&g_cnt[d.w], 1);
}

// ---------------- per-graph node counts, warp-aggregated ----------------
__global__ void k_gcnt(const int* __restrict__ batch) {
    int i = blockIdx.x * blockDim.x + threadIdx.x;
    if (i >= NN) return;
    int b = batch[i];
    unsigned m = __match_any_sync(__activemask(), b);
    int leader = __ffs(m) - 1;
    if ((threadIdx.x & 31) == leader)
        atomicAdd(&g_gcnt[b], __popc(m));
}

// ---------------- exclusive scan of g_cnt -> g_rowptr (warp-shuffle) ----------------
__global__ void k_scanA() {
    __shared__ int wsum[32];
    int i = blockIdx.x * 1024 + threadIdx.x;
    int lane = threadIdx.x & 31, warp = threadIdx.x >> 5;
    int v = (i < NN) ? g_cnt[i] : 0;
    int s = v;
#pragma unroll
    for (int off = 1; off < 32; off <<= 1) {
        int t = __shfl_up_sync(0xffffffffu, s, off);
        if (lane >= off) s += t;
    }
    if (lane == 31) wsum[warp] = s;
    __syncthreads();
    if (warp == 0) {
        int w = wsum[lane];
        int ws = w;
#pragma unroll
        for (int off = 1; off < 32; off <<= 1) {
            int t = __shfl_up_sync(0xffffffffu, ws, off);
            if (lane >= off) ws += t;
        }
        wsum[lane] = ws - w;   // exclusive warp offsets
        if (lane == 31) g_bsum[blockIdx.x] = ws;  // block total
    }
    __syncthreads();
    if (i < NN) g_rowptr[i] = s - v + wsum[warp];
}

__global__ void k_scanB(int nb) {
    if (threadIdx.x == 0) {
        int run = 0;
        for (int i = 0; i < nb; i++) { int t = g_bsum[i]; g_bsum[i] = run; run += t; }
    }
}

// rowptr block offsets + dinv + pre-scaled xs in one pass
__global__ void k_scanC(const float* __restrict__ x) {
    int i = blockIdx.x * blockDim.x + threadIdx.x;
    if (i < NN) {
        g_rowptr[i] += g_bsum[i >> 10];
        float dn = rsqrtf((float)(g_cnt[i] + 1));  // +1 self loop
        g_dinv[i] = dn;
        g_xs[i] = make_float4(dn * __ldg(&x[i * 3]),
                              dn * __ldg(&x[i * 3 + 1]),
                              dn * __ldg(&x[i * 3 + 2]), 0.f);
    }
}

// ---------------- CSR fill: just src index (weights folded into features) ----------------
__global__ void k_fill(const int* __restrict__ ei) {
    int e = blockIdx.x * blockDim.x + threadIdx.x;
    if (e >= NE / 4) return;
    int4 s4 = __ldg(&((const int4*)ei)[e]);
    int4 d4 = __ldg(&((const int4*)(ei + NE))[e]);
#pragma unroll
    for (int j = 0; j < 4; j++) {
        int s = (j == 0) ? s4.x : (j == 1) ? s4.y : (j == 2) ? s4.z : s4.w;
        int d = (j == 0) ? d4.x : (j == 1) ? d4.y : (j == 2) ? d4.z : d4.w;
        int pos = g_rowptr[d] + atomicAdd(&g_cur[d], 1);
        g_col[pos] = s;
    }
}

// ---------------- fused: hs = dinv*relu(conv(x) @ W1 + b1) -> fp16, warp per node ----------------
__global__ void k_conv3h(const float* __restrict__ W1, const float* __restrict__ b1) {
    int n = blockIdx.x * 8 + (threadIdx.x >> 5);
    int lane = threadIdx.x & 31;
    if (n >= NN) return;
    // lane owns output features 2*lane, 2*lane+1
    int f0 = lane * 2;
    float w00 = __ldg(&W1[f0]),       w01 = __ldg(&W1[f0 + 1]);
    float w10 = __ldg(&W1[64 + f0]),  w11 = __ldg(&W1[64 + f0 + 1]);
    float w20 = __ldg(&W1[128 + f0]), w21 = __ldg(&W1[128 + f0 + 1]);
    float bb0 = __ldg(&b1[f0]),       bb1 = __ldg(&b1[f0 + 1]);

    int r0 = g_rowptr[n];
    int r1 = r0 + g_cnt[n];
    float a0 = 0.f, a1 = 0.f, a2 = 0.f;
    for (int i = r0 + lane; i < r1; i += 32) {
        float4 v = __ldg(&g_xs[__ldg(&g_col[i])]);   // xs = dinv[s]*x[s]
        a0 += v.x;
        a1 += v.y;
        a2 += v.z;
    }
#pragma unroll
    for (int off = 16; off > 0; off >>= 1) {
        a0 += __shfl_down_sync(0xffffffffu, a0, off);
        a1 += __shfl_down_sync(0xffffffffu, a1, off);
        a2 += __shfl_down_sync(0xffffffffu, a2, off);
    }
    float dn = g_dinv[n];
    if (lane == 0) {
        float4 v = __ldg(&g_xs[n]);                  // self loop: +xs[n]
        a0 = dn * (a0 + v.x);
        a1 = dn * (a1 + v.y);
        a2 = dn * (a2 + v.z);
    }
    a0 = __shfl_sync(0xffffffffu, a0, 0);
    a1 = __shfl_sync(0xffffffffu, a1, 0);
    a2 = __shfl_sync(0xffffffffu, a2, 0);
    float v0 = fmaxf(bb0 + a0 * w00 + a1 * w10 + a2 * w20, 0.f);
    float v1 = fmaxf(bb1 + a0 * w01 + a1 * w11 + a2 * w21, 0.f);
    // store pre-scaled hs = dinv[n]*h[n]
    g_h[(size_t)n * 32 + lane] = __floats2half2_rn(dn * v0, dn * v1);
}

// ---------------- conv64: g_C = dinv[n]*(sum hs[s] + hs[n]), warp per node ----------------
__global__ void k_conv64() {
    int n = blockIdx.x * 8 + (threadIdx.x >> 5);
    int lane = threadIdx.x & 31;
    if (n >= NN) return;
    int r0 = g_rowptr[n];
    int r1 = r0 + g_cnt[n];
    float ax = 0.f, ay = 0.f;
#pragma unroll 4
    for (int i = r0; i < r1; i++) {
        int s = __ldg(&g_col[i]);            // broadcast 4B
        float2 v = __half22float2(__ldg(&g_h[(size_t)s * 32 + lane]));  // 128B row
        ax += v.x;
        ay += v.y;
    }
    float dn = g_dinv[n];
    float2 v = __half22float2(__ldg(&g_h[(size_t)n * 32 + lane]));
    ax = dn * (ax + v.x);
    ay = dn * (ay + v.y);
    ((float2*)g_C)[(size_t)n * 32 + lane] = make_float2(ax, ay);
}

// ---------------- relu(g_C @ W2 + b2), fused pooling ----------------
__global__ void k_g2p(const float* __restrict__ W2, const float* __restrict__ b2,
                      const int* __restrict__ batch) {
    __shared__ float W2s[64 * 64];          // [k*64 + f]
    __shared__ float hs[32 * 68];           // 32 node rows, padded
    __shared__ float red[4 * 64];           // grp partial sums per feature
    int tid = threadIdx.x;
    int nbase = blockIdx.x * 32;
    for (int i = tid; i < 4096; i += 256) W2s[i] = W2[i];
    for (int i = tid; i < 2048; i += 256) {
        int node = i >> 6, k = i & 63;
        hs[node * 68 + k] = g_C[(size_t)(nbase + node) * 64 + k];
    }
    __syncthreads();
    int f = tid & 63, grp = tid >> 6;       // grp owns 8 nodes
    float bf = __ldg(&b2[f]);
    float acc[8];
#pragma unroll
    for (int i = 0; i < 8; i++) acc[i] = bf;
#pragma unroll 4
    for (int k4 = 0; k4 < 64; k4 += 4) {
        float4 hv[8];
#pragma unroll
        for (int i = 0; i < 8; i++)
            hv[i] = *(const float4*)&hs[(grp * 8 + i) * 68 + k4];
#pragma unroll
        for (int j = 0; j < 4; j++) {
            float wk = W2s[(k4 + j) * 64 + f];
#pragma unroll
            for (int i = 0; i < 8; i++) {
                float h = (j == 0) ? hv[i].x : (j == 1) ? hv[i].y : (j == 2) ? hv[i].z : hv[i].w;
                acc[i] += h * wk;
            }
        }
    }
    int b_lo = __ldg(&batch[nbase]);
    int b_hi = __ldg(&batch[nbase + 31]);
    if (b_lo == b_hi) {
        // whole block is one graph: block-reduce then 64 atomics
        float p = 0.f;
#pragma unroll
        for (int i = 0; i < 8; i++) p += fmaxf(acc[i], 0.f);
        red[grp * 64 + f] = p;
        __syncthreads();
        if (grp == 0) {
            float s = red[f] + red[64 + f] + red[128 + f] + red[192 + f];
            atomicAdd(&g_pool[b_lo * 64 + f], s);
        }
    } else {
        // boundary block (rare): per-node atomics
#pragma unroll
        for (int i = 0; i < 8; i++) {
            int node = nbase + grp * 8 + i;
            atomicAdd(&g_pool[__ldg(&batch[node]) * 64 + f], fmaxf(acc[i], 0.f));
        }
    }
}

// ---------------- out[g] = (sum_f pool[g][f]*Wr[f]) / count + br ----------------
__global__ void k_final(const float* __restrict__ Wr, const float* __restrict__ br,
                        float* __restrict__ out) {
    int g = threadIdx.x;
    if (g >= NG) return;
    float s = 0.f;
#pragma unroll
    for (int f = 0; f < 64; f++) s += g_pool[g * 64 + f] * Wr[f];
    out[g] = s / fmaxf((float)g_gcnt[g], 1.f) + br[0];
}

extern "C" void kernel_launch(void* const* d_in, const int* in_sizes, int n_in,
                              void* d_out, int out_size) {
    const float* x     = (const float*)d_in[0];
    const int*   ei    = (const int*)d_in[1];     // int32
    const int*   batch = (const int*)d_in[2];     // int32
    const float* W1    = (const float*)d_in[3];
    const float* b1    = (const float*)d_in[4];
    const float* W2    = (const float*)d_in[5];
    const float* b2    = (const float*)d_in[6];
    const float* Wr    = (const float*)d_in[7];
    const float* br    = (const float*)d_in[8];
    float*       out   = (float*)d_out;

    (void)in_sizes; (void)n_in; (void)out_size;

    const int nb = (NN + 1023) / 1024;   // 98 scan blocks
    const int eb = (NE / 4 + 255) / 256; // 3125 edge-quad blocks

    k_zero<<<(NN + 255) / 256, 256>>>();
    k_hist<<<eb, 256>>>(ei);
    k_gcnt<<<(NN + 255) / 256, 256>>>(batch);
    k_scanA<<<nb, 1024>>>();
    k_scanB<<<1, 32>>>(nb);
    k_scanC<<<(NN + 255) / 256, 256>>>(x);    // rowptr offsets + dinv + xs
    k_fill<<<eb, 256>>>(ei);

    k_conv3h<<<(NN + 7) / 8, 256>>>(W1, b1);  // hs = dinv*relu(dinv*conv(x)@W1+b1) fp16
    k_conv64<<<(NN + 7) / 8, 256>>>();        // C = dinv*(sum hs + hs_self)
    k_g2p<<<NN / 32, 256>>>(W2, b2, batch);   // pool(relu(C@W2+b2))

    k_final<<<1, 64>>>(Wr, br, out);
}